// round 5
// baseline (speedup 1.0000x reference)
#include <cuda_runtime.h>

// Problem constants (fixed shapes from reference)
#define B_   64
#define G_   128
#define A_   3
#define N_   1280
#define CH_  (A_ * 5)             // 15 floats per (b,gy,gx) cell
#define TOT_ (B_ * G_ * G_ * CH_) // 15,728,640 floats
#define TOT4_ (TOT_ / 4)          // 3,932,160 float4

__device__ __forceinline__ float softplus_f(float v) {
    // log(1 + exp(v)), numerically stable
    float a = fabsf(v);
    return fmaxf(v, 0.0f) + log1pf(expf(-a));
}

__device__ __forceinline__ void block_reduce_add(float s, float scale, float* out) {
    #pragma unroll
    for (int o = 16; o > 0; o >>= 1)
        s += __shfl_down_sync(0xFFFFFFFFu, s, o);
    __shared__ float sm[32];
    int lane = threadIdx.x & 31;
    int wid  = threadIdx.x >> 5;
    if (lane == 0) sm[wid] = s;
    __syncthreads();
    if (wid == 0) {
        int nw = (blockDim.x + 31) >> 5;
        s = (lane < nw) ? sm[lane] : 0.0f;
        #pragma unroll
        for (int o = 16; o > 0; o >>= 1)
            s += __shfl_down_sync(0xFFFFFFFFu, s, o);
        if (lane == 0) atomicAdd(out, s * scale);
    }
}

__global__ void zero_out_kernel(float* out) { out[0] = 0.0f; }

// Dense pass: NOOBJ * sum over every conf logit of softplus(conf).
// Last dim is 15 = 3 anchors x 5; conf sits at channel offsets 0, 5, 10,
// i.e. flat index f with f % 5 == 0.
__global__ void noobj_kernel(const float* __restrict__ yp, float* __restrict__ out) {
    float s = 0.0f;
    int stride = gridDim.x * blockDim.x;
    for (int i = blockIdx.x * blockDim.x + threadIdx.x; i < TOT4_; i += stride) {
        float4 v = reinterpret_cast<const float4*>(yp)[i];
        int r = (i * 4) % 5;  // residue of lane .x
        if (r == 0) s += softplus_f(v.x);
        if (r == 4) s += softplus_f(v.y);  // (4i+1)%5==0
        if (r == 3) s += softplus_f(v.z);  // (4i+2)%5==0
        if (r == 2) s += softplus_f(v.w);  // (4i+3)%5==0
    }
    block_reduce_add(s, 0.5f /*NOOBJ_L*/, out);
}

// Sparse pass: per ground-truth box, correction at its target cell:
//   - NOOBJ*softplus(conf)   (remove dense noobj contribution, m=1 there)
//   + OBJ*softplus(-conf)    (objectness)
//   + COORD*MSE(x,y,w,h)
__global__ void box_kernel(const float* __restrict__ yp,
                           const float* __restrict__ boxes,
                           const float* __restrict__ anchors,
                           const int*   __restrict__ bidx,
                           float* __restrict__ out) {
    const float inv_stride = 1.0f / 8.0f;  // stride = 1024/128 = 8
    int i = blockIdx.x * blockDim.x + threadIdx.x;
    float c = 0.0f;
    if (i < N_) {
        float gx = boxes[i * 4 + 0] * inv_stride;
        float gy = boxes[i * 4 + 1] * inv_stride;
        float gw = boxes[i * 4 + 2] * inv_stride;
        float gh = boxes[i * 4 + 3] * inv_stride;
        int gi = (int)gx;
        int gj = (int)gy;

        // argmax IoU over 3 anchors (ties -> first index, matching jnp.argmax)
        int best = 0;
        float bestv = -1.0f;
        float baw = 0.0f, bah = 0.0f;
        #pragma unroll
        for (int a = 0; a < A_; a++) {
            float aw = anchors[2 * a + 0] * inv_stride;
            float ah = anchors[2 * a + 1] * inv_stride;
            float inter = fminf(aw, gw) * fminf(ah, gh);
            float uni = aw * ah + gw * gh - inter;
            float iou = inter / uni;
            if (iou > bestv) { bestv = iou; best = a; baw = aw; bah = ah; }
        }

        float tx = gx - (float)gi;
        float ty = gy - (float)gj;
        float tw = logf(gw / baw);
        float th = logf(gh / bah);

        int b = bidx[i];
        const float* p = yp + ((size_t)((b * G_ + gj) * G_ + gi)) * CH_ + best * 5;
        float conf = p[0];
        float x = 1.0f / (1.0f + expf(-p[1]));
        float y = 1.0f / (1.0f + expf(-p[2]));
        float w = p[3];
        float h = p[4];

        float dx = x - tx, dy = y - ty, dw = w - tw, dh = h - th;
        c = -0.5f /*NOOBJ_L*/ * softplus_f(conf)
          +  1.0f /*OBJ_L*/   * softplus_f(-conf)
          +  5.0f /*COORD_L*/ * (dx * dx + dy * dy + dw * dw + dh * dh);
    }
    block_reduce_add(c, 1.0f, out);
}

extern "C" void kernel_launch(void* const* d_in, const int* in_sizes, int n_in,
                              void* d_out, int out_size) {
    const float* y_pred  = (const float*)d_in[0];
    const float* boxes   = (const float*)d_in[1];
    const float* anchors = (const float*)d_in[2];
    const int*   bidx    = (const int*)d_in[3];
    float* out = (float*)d_out;

    zero_out_kernel<<<1, 1>>>(out);
    // HBM-bound dense reduction: 62.9 MB read. 2368 blocks x 256 thr, grid-stride.
    noobj_kernel<<<2368, 256>>>(y_pred, out);
    box_kernel<<<(N_ + 255) / 256, 256>>>(y_pred, boxes, anchors, bidx, out);
}

// round 6
// speedup vs baseline: 1.2986x; 1.2986x over previous
#include <cuda_runtime.h>

// Problem constants (fixed shapes from reference)
#define B_    64
#define G_    128
#define A_    3
#define N_    1280
#define CH_   (A_ * 5)             // 15 floats per (b,gy,gx) cell
#define TOT_  (B_ * G_ * G_ * CH_) // 15,728,640 floats
#define TOT4_ (TOT_ / 4)           // 3,932,160 float4

#define GRID_   2368
#define BLOCK_  256

// Scratch for single-kernel two-phase reduction (allowed: __device__ globals).
__device__ float        g_partials[GRID_];
__device__ unsigned int g_done = 0;   // self-resetting via atomicInc wrap

__device__ __forceinline__ float softplus_fast(float v) {
    // log(1+exp(v)) = max(v,0) + log(1+exp(-|v|)); fast intrinsics.
    float a = fabsf(v);
    return fmaxf(v, 0.0f) + __logf(1.0f + __expf(-a));
}

// Block reduce; returns full block sum on thread 0 (garbage elsewhere).
__device__ __forceinline__ float block_reduce(float s) {
    #pragma unroll
    for (int o = 16; o > 0; o >>= 1)
        s += __shfl_down_sync(0xFFFFFFFFu, s, o);
    __shared__ float sm[BLOCK_ / 32];
    int lane = threadIdx.x & 31;
    int wid  = threadIdx.x >> 5;
    if (lane == 0) sm[wid] = s;
    __syncthreads();
    if (wid == 0) {
        s = (lane < (BLOCK_ / 32)) ? sm[lane] : 0.0f;
        #pragma unroll
        for (int o = 16; o > 0; o >>= 1)
            s += __shfl_down_sync(0xFFFFFFFFu, s, o);
    }
    return s;
}

__global__ void __launch_bounds__(BLOCK_)
yolo_loss_kernel(const float* __restrict__ yp,
                 const float* __restrict__ boxes,
                 const float* __restrict__ anchors,
                 const int*   __restrict__ bidx,
                 float* __restrict__ out) {
    const int tid  = threadIdx.x;
    const int gidx = blockIdx.x * BLOCK_ + tid;

    // ---- Sparse pass (first 5 blocks; 1280 boxes) -------------------------
    float s_box = 0.0f;
    if (gidx < N_) {
        const float inv_stride = 1.0f / 8.0f;  // stride = 1024/128 = 8
        float gx = boxes[gidx * 4 + 0] * inv_stride;
        float gy = boxes[gidx * 4 + 1] * inv_stride;
        float gw = boxes[gidx * 4 + 2] * inv_stride;
        float gh = boxes[gidx * 4 + 3] * inv_stride;
        int gi = (int)gx;
        int gj = (int)gy;

        // argmax IoU over 3 anchors (ties -> first index, matching jnp.argmax)
        int   best  = 0;
        float bestv = -1.0f, baw = 0.0f, bah = 0.0f;
        #pragma unroll
        for (int a = 0; a < A_; a++) {
            float aw = anchors[2 * a + 0] * inv_stride;
            float ah = anchors[2 * a + 1] * inv_stride;
            float inter = fminf(aw, gw) * fminf(ah, gh);
            float uni   = aw * ah + gw * gh - inter;
            float iou   = inter / uni;
            if (iou > bestv) { bestv = iou; best = a; baw = aw; bah = ah; }
        }

        float tx = gx - (float)gi;
        float ty = gy - (float)gj;
        float tw = __logf(gw / baw);
        float th = __logf(gh / bah);

        int b = bidx[gidx];
        const float* p = yp + ((size_t)((b * G_ + gj) * G_ + gi)) * CH_ + best * 5;
        float conf = p[0];
        float x = 1.0f / (1.0f + __expf(-p[1]));
        float y = 1.0f / (1.0f + __expf(-p[2]));
        float w = p[3];
        float h = p[4];

        float dx = x - tx, dy = y - ty, dw = w - tw, dh = h - th;
        s_box = -0.5f /*NOOBJ*/ * softplus_fast(conf)
              +  1.0f /*OBJ*/   * softplus_fast(-conf)
              +  5.0f /*COORD*/ * (dx * dx + dy * dy + dw * dw + dh * dh);
    }

    // ---- Dense pass: sum softplus over every conf logit (f % 5 == 0) ------
    float s_dense = 0.0f;
    const int stride = GRID_ * BLOCK_;
    for (int i = gidx; i < TOT4_; i += stride) {
        float4 v = reinterpret_cast<const float4*>(yp)[i];
        int r = (i * 4) % 5;  // residue of lane .x
        if (r == 0) s_dense += softplus_fast(v.x);
        if (r == 4) s_dense += softplus_fast(v.y);  // (4i+1)%5==0
        if (r == 3) s_dense += softplus_fast(v.z);  // (4i+2)%5==0
        if (r == 2) s_dense += softplus_fast(v.w);  // (4i+3)%5==0
    }

    // ---- Two-phase reduction in one kernel --------------------------------
    float bsum = block_reduce(0.5f /*NOOBJ*/ * s_dense + s_box);

    __shared__ bool is_last;
    if (tid == 0) {
        g_partials[blockIdx.x] = bsum;
        __threadfence();
        // atomicInc wraps to 0 at GRID_-1 -> counter self-resets each launch.
        unsigned prev = atomicInc(&g_done, GRID_ - 1);
        is_last = (prev == GRID_ - 1);
    }
    __syncthreads();

    if (is_last) {
        __threadfence();  // make all partials visible to this block
        float s = 0.0f;
        for (int i = tid; i < GRID_; i += BLOCK_)
            s += g_partials[i];
        float total = block_reduce(s);
        if (tid == 0) out[0] = total;
    }
}

extern "C" void kernel_launch(void* const* d_in, const int* in_sizes, int n_in,
                              void* d_out, int out_size) {
    const float* y_pred  = (const float*)d_in[0];
    const float* boxes   = (const float*)d_in[1];
    const float* anchors = (const float*)d_in[2];
    const int*   bidx    = (const int*)d_in[3];
    float* out = (float*)d_out;

    yolo_loss_kernel<<<GRID_, BLOCK_>>>(y_pred, boxes, anchors, bidx, out);
}

// round 7
// speedup vs baseline: 2.0550x; 1.5825x over previous
#include <cuda_runtime.h>

// Problem constants (fixed shapes from reference)
#define B_    64
#define G_    128
#define A_    3
#define N_    1280
#define CH_   (A_ * 5)             // 15 floats per (b,gy,gx) cell
#define TOT_  (B_ * G_ * G_ * CH_) // 15,728,640 floats
#define TOT4_ (TOT_ / 4)           // 3,932,160 float4
// Dense j-space: float4s that contain a conf value (4 of every 5 float4s).
#define NJ_   (TOT4_ / 5 * 4)      // 3,145,728

#define GRID_   2368
#define BLOCK_  256

// Scratch for single-kernel two-phase reduction (allowed: __device__ globals).
__device__ float        g_partials[GRID_];
__device__ unsigned int g_done = 0;   // self-resetting via atomicInc wrap

__device__ __forceinline__ float softplus_fast(float v) {
    // log(1+exp(v)) = max(v,0) + log(1+exp(-|v|)); fast intrinsics (2 MUFU).
    float a = fabsf(v);
    return fmaxf(v, 0.0f) + __logf(1.0f + __expf(-a));
}

// Block reduce; returns full block sum on thread 0 (garbage elsewhere).
__device__ __forceinline__ float block_reduce(float s) {
    #pragma unroll
    for (int o = 16; o > 0; o >>= 1)
        s += __shfl_down_sync(0xFFFFFFFFu, s, o);
    __shared__ float sm[BLOCK_ / 32];
    int lane = threadIdx.x & 31;
    int wid  = threadIdx.x >> 5;
    if (lane == 0) sm[wid] = s;
    __syncthreads();
    if (wid == 0) {
        s = (lane < (BLOCK_ / 32)) ? sm[lane] : 0.0f;
        #pragma unroll
        for (int o = 16; o > 0; o >>= 1)
            s += __shfl_down_sync(0xFFFFFFFFu, s, o);
    }
    return s;
}

__global__ void __launch_bounds__(BLOCK_)
yolo_loss_kernel(const float* __restrict__ yp,
                 const float* __restrict__ boxes,
                 const float* __restrict__ anchors,
                 const int*   __restrict__ bidx,
                 float* __restrict__ out) {
    const int tid  = threadIdx.x;
    const int gidx = blockIdx.x * BLOCK_ + tid;

    // ---- Sparse pass (first 5 blocks; 1280 boxes) -------------------------
    float s_box = 0.0f;
    if (gidx < N_) {
        const float inv_stride = 1.0f / 8.0f;  // stride = 1024/128 = 8
        float gx = boxes[gidx * 4 + 0] * inv_stride;
        float gy = boxes[gidx * 4 + 1] * inv_stride;
        float gw = boxes[gidx * 4 + 2] * inv_stride;
        float gh = boxes[gidx * 4 + 3] * inv_stride;
        int gi = (int)gx;
        int gj = (int)gy;

        // argmax IoU over 3 anchors (ties -> first index, matching jnp.argmax)
        int   best  = 0;
        float bestv = -1.0f, baw = 0.0f, bah = 0.0f;
        #pragma unroll
        for (int a = 0; a < A_; a++) {
            float aw = anchors[2 * a + 0] * inv_stride;
            float ah = anchors[2 * a + 1] * inv_stride;
            float inter = fminf(aw, gw) * fminf(ah, gh);
            float uni   = aw * ah + gw * gh - inter;
            float iou   = inter / uni;
            if (iou > bestv) { bestv = iou; best = a; baw = aw; bah = ah; }
        }

        float tx = gx - (float)gi;
        float ty = gy - (float)gj;
        float tw = __logf(gw / baw);
        float th = __logf(gh / bah);

        int b = bidx[gidx];
        const float* p = yp + ((size_t)((b * G_ + gj) * G_ + gi)) * CH_ + best * 5;
        float conf = p[0];
        float x = 1.0f / (1.0f + __expf(-p[1]));
        float y = 1.0f / (1.0f + __expf(-p[2]));
        float w = p[3];
        float h = p[4];

        float dx = x - tx, dy = y - ty, dw = w - tw, dh = h - th;
        s_box = -0.5f /*NOOBJ*/ * softplus_fast(conf)
              +  1.0f /*OBJ*/   * softplus_fast(-conf)
              +  5.0f /*COORD*/ * (dx * dx + dy * dy + dw * dw + dh * dh);
    }

    // ---- Dense pass: sum softplus over every conf logit ------------------
    // Channel period = 20 floats = 5 float4s; float4 i (i%5<4) holds exactly
    // one conf at component i%5; i%5==4 holds none and is never loaded.
    // Map j -> i = j + (j>>2): enumerates exactly the conf-bearing float4s.
    // Component index = j&3 is loop-invariant per thread (stride % 4 == 0).
    float s_dense = 0.0f;
    const int stride = GRID_ * BLOCK_;   // multiple of 4
    const int comp = gidx & 3;
    const float4* yp4 = reinterpret_cast<const float4*>(yp);
    for (int j = gidx; j < NJ_; j += stride) {
        int i = j + (j >> 2);
        float4 v = yp4[i];
        float c = (comp == 0) ? v.x : (comp == 1) ? v.y : (comp == 2) ? v.z : v.w;
        s_dense += softplus_fast(c);
    }

    // ---- Two-phase reduction in one kernel --------------------------------
    float bsum = block_reduce(0.5f /*NOOBJ*/ * s_dense + s_box);

    __shared__ bool is_last;
    if (tid == 0) {
        g_partials[blockIdx.x] = bsum;
        __threadfence();
        // atomicInc wraps to 0 at GRID_-1 -> counter self-resets each launch.
        unsigned prev = atomicInc(&g_done, GRID_ - 1);
        is_last = (prev == GRID_ - 1);
    }
    __syncthreads();

    if (is_last) {
        __threadfence();  // make all partials visible to this block
        float s = 0.0f;
        for (int i = tid; i < GRID_; i += BLOCK_)
            s += g_partials[i];
        float total = block_reduce(s);
        if (tid == 0) out[0] = total;
    }
}

extern "C" void kernel_launch(void* const* d_in, const int* in_sizes, int n_in,
                              void* d_out, int out_size) {
    const float* y_pred  = (const float*)d_in[0];
    const float* boxes   = (const float*)d_in[1];
    const float* anchors = (const float*)d_in[2];
    const int*   bidx    = (const int*)d_in[3];
    float* out = (float*)d_out;

    yolo_loss_kernel<<<GRID_, BLOCK_>>>(y_pred, boxes, anchors, bidx, out);
}